// round 15
// baseline (speedup 1.0000x reference)
#include <cuda_runtime.h>
#include <cuda_bf16.h>
#include <mma.h>

using namespace nvcuda;

#define N0 262144
#define N1 32768
#define N2 4096
#define BN_EPS 1e-5f

typedef unsigned long long u64;
typedef unsigned int u32;

__device__ __forceinline__ u64 pack2(float v) {
    u64 r; asm("mov.b64 %0, {%1, %1};" : "=l"(r) : "f"(v)); return r;
}
__device__ __forceinline__ void fma2(u64& d, u64 a, u64 b) {
    asm("fma.rn.f32x2 %0, %1, %2, %0;" : "+l"(d) : "l"(a), "l"(b));
}
__device__ __forceinline__ void unpack2(u64 v, float& lo, float& hi) {
    asm("mov.b64 {%0, %1}, %2;" : "=f"(lo), "=f"(hi) : "l"(v));
}
__device__ __forceinline__ void cp16(void* smem, const void* gmem) {
    u32 sa = (u32)__cvta_generic_to_shared(smem);
    asm volatile("cp.async.cg.shared.global [%0], [%1], 16;" :: "r"(sa), "l"(gmem));
}
__device__ __forceinline__ void cp_commit() { asm volatile("cp.async.commit_group;"); }
template <int W_> __device__ __forceinline__ void cp_wait() {
    asm volatile("cp.async.wait_group %0;" :: "n"(W_));
}
__device__ __forceinline__ u32 pack_bf16x2(float a, float b) {
    __nv_bfloat162 t = __floats2bfloat162_rn(a, b);
    return *(u32*)&t;
}

// ---------------- static scratch ----------------
__device__ float4 g_x4[N0];
__device__ float g_y0[N0 * 24];
__device__ float g_y1[N1 * 48];
__device__ float g_y2[N1 * 48];
__device__ float g_y3[N2 * 96];
__device__ __nv_bfloat16 g_y1hl[N1 * 128];   // 256B rows: hi@0(96B pad 128), lo@128B
__device__ __nv_bfloat16 g_y3hl[N2 * 256];   // 512B rows: hi@0(192B pad 256), lo@256B
__device__ __nv_bfloat16 g_wh[27 * 48 * 48];
__device__ __nv_bfloat16 g_wl[27 * 48 * 48];
__device__ __nv_bfloat16 g_wph[27 * 96 * 96];
__device__ __nv_bfloat16 g_wpl[27 * 96 * 96];
__device__ float g_pD[8 * N2 * 96];
__device__ float g_pE[3 * N2 * 96];
__device__ float g_stats[5 * 192];
__device__ float g_sb[5 * 192];
__device__ u32   g_ctr[8];

// pad + init + W1/Wp bf16-splits, all fused
__global__ void pad_kernel(const float* __restrict__ d, const float* __restrict__ w1,
                           const float* __restrict__ wp) {
    int i = blockIdx.x * 256 + threadIdx.x;
    if (blockIdx.x == 0) {
        int t = threadIdx.x;
        for (int j = t; j < 5 * 192; j += 256) g_stats[j] = 0.f;
        if (t < 8) g_ctr[t] = 0u;
    }
    if (i < 27 * 48 * 48) {
        float w = w1[i];
        __nv_bfloat16 h = __float2bfloat16(w);
        g_wh[i] = h;
        g_wl[i] = __float2bfloat16(w - __bfloat162float(h));
    }
    if (i < 27 * 96 * 96) {
        float w = wp[i];
        __nv_bfloat16 h = __float2bfloat16(w);
        g_wph[i] = h;
        g_wpl[i] = __float2bfloat16(w - __bfloat162float(h));
    }
    if (i < N0) {
        float4 v;
        v.x = d[3 * i]; v.y = d[3 * i + 1]; v.z = d[3 * i + 2]; v.w = 0.f;
        g_x4[i] = v;
    }
}

// y1 + sb1 -> BN+ReLU -> interleaved padded bf16 hi/lo rows (256B stride)
__global__ void __launch_bounds__(256) prepY_kernel(
    const float* __restrict__ y1, const float* __restrict__ sb)
{
    int idx = blockIdx.x * 256 + threadIdx.x;
    if (idx >= N1 * 12) return;
    int e = idx * 4;
    int row = e / 48, c = e % 48;
    float4 v = *(const float4*)(y1 + e);
    v.x = fmaxf(v.x * sb[c + 0] + sb[48 + c + 0], 0.f);
    v.y = fmaxf(v.y * sb[c + 1] + sb[48 + c + 1], 0.f);
    v.z = fmaxf(v.z * sb[c + 2] + sb[48 + c + 2], 0.f);
    v.w = fmaxf(v.w * sb[c + 3] + sb[48 + c + 3], 0.f);
    u32 h01 = pack_bf16x2(v.x, v.y);
    u32 h23 = pack_bf16x2(v.z, v.w);
    float2 f01 = __bfloat1622float2(*(__nv_bfloat162*)&h01);
    float2 f23 = __bfloat1622float2(*(__nv_bfloat162*)&h23);
    u32 l01 = pack_bf16x2(v.x - f01.x, v.y - f01.y);
    u32 l23 = pack_bf16x2(v.z - f23.x, v.w - f23.y);
    *(u64*)(g_y1hl + row * 128 + c)      = (u64)h01 | ((u64)h23 << 32);
    *(u64*)(g_y1hl + row * 128 + 64 + c) = (u64)l01 | ((u64)l23 << 32);
}

// y3 + sb3 -> BN+ReLU -> interleaved padded bf16 hi/lo rows (512B stride)
__global__ void __launch_bounds__(256) prepE_kernel(
    const float* __restrict__ y3, const float* __restrict__ sb)
{
    int idx = blockIdx.x * 256 + threadIdx.x;
    if (idx >= N2 * 24) return;
    int e = idx * 4;
    int row = e / 96, c = e % 96;
    float4 v = *(const float4*)(y3 + e);
    v.x = fmaxf(v.x * sb[c + 0] + sb[96 + c + 0], 0.f);
    v.y = fmaxf(v.y * sb[c + 1] + sb[96 + c + 1], 0.f);
    v.z = fmaxf(v.z * sb[c + 2] + sb[96 + c + 2], 0.f);
    v.w = fmaxf(v.w * sb[c + 3] + sb[96 + c + 3], 0.f);
    u32 h01 = pack_bf16x2(v.x, v.y);
    u32 h23 = pack_bf16x2(v.z, v.w);
    float2 f01 = __bfloat1622float2(*(__nv_bfloat162*)&h01);
    float2 f23 = __bfloat1622float2(*(__nv_bfloat162*)&h23);
    u32 l01 = pack_bf16x2(v.x - f01.x, v.y - f01.y);
    u32 l23 = pack_bf16x2(v.z - f23.x, v.w - f23.y);
    *(u64*)(g_y3hl + row * 256 + c)       = (u64)h01 | ((u64)h23 << 32);
    *(u64*)(g_y3hl + row * 256 + 128 + c) = (u64)l01 | ((u64)l23 << 32);
}

// ---------------------------------------------------------------------------
// Stage A: per-thread, 2 rows/thread, CIN=3 -> COUT=24, K=27. Fused stats.
// ---------------------------------------------------------------------------
__global__ void __launch_bounds__(256, 2) convA_kernel(
    const float4* __restrict__ x4, const int* __restrict__ neigh,
    const float* __restrict__ W, float* __restrict__ y,
    float* __restrict__ stats, const float* __restrict__ g,
    const float* __restrict__ b, float* __restrict__ sbout,
    u32* __restrict__ ctr)
{
    __shared__ __align__(16) float sh_w[27 * 3 * 24];
    __shared__ int sh_idx[512 * 3];
    __shared__ float sh_stat[8 * 48];
    __shared__ bool s_last;

    const int tid = threadIdx.x;
    const int n0 = blockIdx.x * 512;

    for (int i = tid; i < 27 * 3 * 24 / 4; i += 256) cp16(sh_w + 4 * i, W + 4 * i);
    cp_commit(); cp_wait<0>();

    u64 acc[2][12] = {};

    #pragma unroll 1
    for (int kt = 0; kt < 27; kt += 3) {
        __syncthreads();
        #pragma unroll 1
        for (int i = tid; i < 512 * 3; i += 256) {
            int row = i / 3, kk = i % 3;
            sh_idx[i] = neigh[(size_t)(n0 + row) * 27 + kt + kk];
        }
        __syncthreads();
        #pragma unroll
        for (int k2 = 0; k2 < 3; ++k2) {
            int i0 = sh_idx[(2 * tid) * 3 + k2];
            int i1 = sh_idx[(2 * tid + 1) * 3 + k2];
            float4 v0 = x4[i0], v1 = x4[i1];
            const float* wk = sh_w + (kt + k2) * 72;
            #pragma unroll
            for (int c = 0; c < 3; ++c) {
                u64 p0 = pack2(c == 0 ? v0.x : (c == 1 ? v0.y : v0.z));
                u64 p1 = pack2(c == 0 ? v1.x : (c == 1 ? v1.y : v1.z));
                const ulonglong2* wr = (const ulonglong2*)(wk + c * 24);
                #pragma unroll
                for (int j = 0; j < 6; ++j) {
                    ulonglong2 wv = wr[j];
                    fma2(acc[0][2 * j],     p0, wv.x);
                    fma2(acc[0][2 * j + 1], p0, wv.y);
                    fma2(acc[1][2 * j],     p1, wv.x);
                    fma2(acc[1][2 * j + 1], p1, wv.y);
                }
            }
        }
    }

    #pragma unroll
    for (int r = 0; r < 2; ++r) {
        u64* yr = (u64*)(y + (size_t)(n0 + 2 * tid + r) * 24);
        #pragma unroll
        for (int j = 0; j < 12; ++j) yr[j] = acc[r][j];
    }

    const int wid = tid >> 5;
    #pragma unroll 1
    for (int j = 0; j < 12; ++j) {
        float lo0, hi0, lo1, hi1;
        unpack2(acc[0][j], lo0, hi0);
        unpack2(acc[1][j], lo1, hi1);
        float s0 = lo0 + lo1, s1 = hi0 + hi1;
        float q0 = lo0 * lo0 + lo1 * lo1, q1 = hi0 * hi0 + hi1 * hi1;
        #pragma unroll
        for (int o = 16; o; o >>= 1) {
            s0 += __shfl_xor_sync(~0u, s0, o);
            s1 += __shfl_xor_sync(~0u, s1, o);
            q0 += __shfl_xor_sync(~0u, q0, o);
            q1 += __shfl_xor_sync(~0u, q1, o);
        }
        if ((tid & 31) == 0) {
            float* row = sh_stat + wid * 48;
            row[2 * j] = s0;  row[2 * j + 1] = s1;
            row[24 + 2 * j] = q0;  row[24 + 2 * j + 1] = q1;
        }
    }
    __syncthreads();
    if (tid < 48) {
        float t = 0.f;
        #pragma unroll
        for (int w = 0; w < 8; ++w) t += sh_stat[w * 48 + tid];
        atomicAdd(&stats[tid], t);
    }
    __syncthreads();
    if (tid == 0) {
        __threadfence();
        s_last = (atomicAdd(ctr, 1u) == gridDim.x - 1);
    }
    __syncthreads();
    if (s_last && tid < 24) {
        float su = __ldcg(&stats[tid]);
        float qq = __ldcg(&stats[24 + tid]);
        float mu = su / (float)N0;
        float var = fmaxf(qq / (float)N0 - mu * mu, 0.f);
        float sc = g[tid] * rsqrtf(var + BN_EPS);
        sbout[tid] = sc;
        sbout[24 + tid] = b[tid] - mu * sc;
    }
}

// ---------------------------------------------------------------------------
// Scalar tiled gather-GEMM (stages B, D). 128-thread block, 64-row tile.
// ---------------------------------------------------------------------------
template <int K, int KPB, int CIN, int COUT, int TD, bool NORM_IN, bool FUSE>
__global__ void __launch_bounds__(128, (TD == 6 ? 6 : 4)) gemm_kernel(
    const float* __restrict__ x, const int* __restrict__ neigh,
    const float* __restrict__ W, const float* __restrict__ sb,
    float* __restrict__ y, int N,
    float* __restrict__ stats, const float* __restrict__ g,
    const float* __restrict__ b, float* __restrict__ sbout,
    u32* __restrict__ ctr, float invN)
{
    constexpr int CC = 24;
    constexpr int NCC = CIN / CC;
    constexpr int CHUNKS = KPB * NCC;
    constexpr int DG = COUT / TD;
    constexpr int XP = 68;
    constexpr int NW = 4;

    __shared__ float sh_x[2][CC * XP];
    __shared__ __align__(16) float sh_w[2][CC * COUT];
    __shared__ float sh_s[NORM_IN ? 2 * CIN : 1];
    __shared__ float sh_stat[FUSE ? NW * 2 * COUT : 1];
    __shared__ bool s_last;

    const int tid = threadIdx.x;
    const int n0 = blockIdx.x * 64;
    const int k0 = blockIdx.z * KPB;
    const int rg = tid / DG;
    const int td = tid % DG;

    auto stageW = [&](int chunk) {
        int k = chunk / NCC, cc = chunk % NCC;
        const float* src = W + ((size_t)(k0 + k) * CIN + cc * CC) * COUT;
        float* dst = sh_w[chunk & 1];
        #pragma unroll 1
        for (int i = tid; i < CC * COUT / 4; i += 128) cp16(dst + 4 * i, src + 4 * i);
        cp_commit();
    };
    auto gather = [&](int chunk, float4* xr) {
        int k = chunk / NCC, cc = chunk % NCC;
        #pragma unroll
        for (int j = 0; j < 3; ++j) {
            int m = tid + 128 * j;
            int row = m / 6, f4 = m % 6;
            int gi = __ldg(&neigh[(size_t)(n0 + row) * K + k0 + k]);
            xr[j] = *(const float4*)(x + (size_t)gi * CIN + cc * CC + f4 * 4);
        }
    };
    auto stsX = [&](int chunk, const float4* xr) {
        int cc = chunk % NCC;
        float* dst = sh_x[chunk & 1];
        #pragma unroll
        for (int j = 0; j < 3; ++j) {
            int m = tid + 128 * j;
            int row = m / 6, f4 = m % 6;
            float4 v = xr[j];
            if (NORM_IN) {
                int gc = cc * CC + 4 * f4;
                v.x = fmaxf(v.x * sh_s[gc + 0] + sh_s[CIN + gc + 0], 0.f);
                v.y = fmaxf(v.y * sh_s[gc + 1] + sh_s[CIN + gc + 1], 0.f);
                v.z = fmaxf(v.z * sh_s[gc + 2] + sh_s[CIN + gc + 2], 0.f);
                v.w = fmaxf(v.w * sh_s[gc + 3] + sh_s[CIN + gc + 3], 0.f);
            }
            dst[(4 * f4 + 0) * XP + row] = v.x;
            dst[(4 * f4 + 1) * XP + row] = v.y;
            dst[(4 * f4 + 2) * XP + row] = v.z;
            dst[(4 * f4 + 3) * XP + row] = v.w;
        }
    };

    u64 acc[4][TD / 2] = {};
    float4 xr[3];

    stageW(0);
    if (NORM_IN)
        for (int i = tid; i < 2 * CIN; i += 128) sh_s[i] = sb[i];
    gather(0, xr);
    cp_wait<0>();
    __syncthreads();
    stsX(0, xr);

    #pragma unroll 1
    for (int i = 0; i < CHUNKS; ++i) {
        __syncthreads();
        if (i + 1 < CHUNKS) { gather(i + 1, xr); stageW(i + 1); }

        const float* wb = sh_w[i & 1];
        const float* xb = sh_x[i & 1];
        #pragma unroll
        for (int c = 0; c < CC; ++c) {
            float4 xv = *(const float4*)&xb[c * XP + 4 * rg];
            u64 P[4] = {pack2(xv.x), pack2(xv.y), pack2(xv.z), pack2(xv.w)};
            const float* wc = wb + c * COUT + td * TD;
            u64 wv[TD / 2];
            if (TD == 6) {
                wv[0] = *(const u64*)(wc + 0);
                wv[1] = *(const u64*)(wc + 2);
                wv[2] = *(const u64*)(wc + 4);
            } else {
                ulonglong2 q0 = *(const ulonglong2*)(wc + 0);
                ulonglong2 q1 = *(const ulonglong2*)(wc + 4);
                ulonglong2 q2 = *(const ulonglong2*)(wc + 8);
                wv[0] = q0.x; wv[1] = q0.y; wv[2] = q1.x;
                wv[3] = q1.y; wv[4] = q2.x; wv[5] = q2.y;
            }
            #pragma unroll
            for (int r = 0; r < 4; ++r)
                #pragma unroll
                for (int j = 0; j < TD / 2; ++j)
                    fma2(acc[r][j], P[r], wv[j]);
        }

        if (i + 1 < CHUNKS) stsX(i + 1, xr);
        cp_wait<0>();
    }

    #pragma unroll
    for (int r = 0; r < 4; ++r) {
        float* yr = y + ((size_t)blockIdx.z * N + n0 + 4 * rg + r) * COUT + td * TD;
        #pragma unroll
        for (int j = 0; j < TD / 2; ++j) *(u64*)(yr + 2 * j) = acc[r][j];
    }

    if (FUSE) {
        const int w = tid >> 5, lane = tid & 31;
        float sA[TD], qA[TD];
        #pragma unroll
        for (int j = 0; j < TD / 2; ++j) {
            float s0 = 0.f, s1 = 0.f, q0 = 0.f, q1 = 0.f;
            #pragma unroll
            for (int r = 0; r < 4; ++r) {
                float lo, hi; unpack2(acc[r][j], lo, hi);
                s0 += lo; s1 += hi; q0 += lo * lo; q1 += hi * hi;
            }
            sA[2 * j] = s0; sA[2 * j + 1] = s1;
            qA[2 * j] = q0; qA[2 * j + 1] = q1;
        }
        #pragma unroll
        for (int o = 8; o < 32; o <<= 1)
            #pragma unroll
            for (int t = 0; t < TD; ++t) {
                sA[t] += __shfl_xor_sync(~0u, sA[t], o);
                qA[t] += __shfl_xor_sync(~0u, qA[t], o);
            }
        if (lane < 8) {
            int base = w * 2 * COUT;
            #pragma unroll
            for (int t = 0; t < TD; ++t) {
                sh_stat[base + lane * TD + t] = sA[t];
                sh_stat[base + COUT + lane * TD + t] = qA[t];
            }
        }
        __syncthreads();
        if (tid < 2 * COUT) {
            float tot = 0.f;
            #pragma unroll
            for (int w2 = 0; w2 < NW; ++w2) tot += sh_stat[w2 * 2 * COUT + tid];
            atomicAdd(&stats[tid], tot);
        }
        __syncthreads();
        if (tid == 0) {
            __threadfence();
            s_last = (atomicAdd(ctr, 1u) == gridDim.x - 1);
        }
        __syncthreads();
        if (s_last && tid < COUT) {
            float su = __ldcg(&stats[tid]);
            float qq = __ldcg(&stats[COUT + tid]);
            float mu = su * invN;
            float var = fmaxf(qq * invN - mu * mu, 0.f);
            float sc = g[tid] * rsqrtf(var + BN_EPS);
            sbout[tid] = sc;
            sbout[COUT + tid] = b[tid] - mu * sc;
        }
    }
}

// ---------------------------------------------------------------------------
// Stage C: monolithic wmma, properly pipelined waits. Fused stats+finalize.
// ---------------------------------------------------------------------------
__global__ void __launch_bounds__(256, 2) convC_wmma(
    const __nv_bfloat16* __restrict__ xhl, const int* __restrict__ neigh,
    const __nv_bfloat16* __restrict__ wh, const __nv_bfloat16* __restrict__ wl,
    float* __restrict__ y,
    float* __restrict__ stats, const float* __restrict__ g,
    const float* __restrict__ b, float* __restrict__ sbout,
    u32* __restrict__ ctr)
{
    extern __shared__ __align__(16) char dsm[];
    __shared__ float sh_stat[4 * 96];
    __shared__ bool s_last;

    const int tid = threadIdx.x;
    const int wid = tid >> 5;
    const int n0 = blockIdx.x * 128;

    const int rp = tid >> 4;
    const int ch = tid & 15;
    const bool isHi = ch < 6;
    const bool isLo = (ch >= 8 && ch < 14);

    auto stage = [&](int k) {
        char* base = dsm + (k & 1) * 39424;
        #pragma unroll
        for (int p = 0; p < 8; ++p) {
            int row = p * 16 + rp;
            int gi = __ldg(&neigh[(size_t)(n0 + row) * 27 + k]);
            const char* src = (const char*)(xhl + (size_t)gi * 128) + ch * 16;
            if (isHi)      cp16(base + row * 112 + ch * 16, src);
            else if (isLo) cp16(base + 14336 + row * 112 + (ch - 8) * 16, src);
        }
        const char* swh = (const char*)(wh + (size_t)k * 2304);
        const char* swl = (const char*)(wl + (size_t)k * 2304);
        #pragma unroll
        for (int t = tid; t < 288; t += 256) {
            int row = t / 6, cc = t % 6;
            cp16(base + 28672 + row * 112 + cc * 16, swh + t * 16);
            cp16(base + 34048 + row * 112 + cc * 16, swl + t * 16);
        }
        cp_commit();
    };

    wmma::fragment<wmma::accumulator, 16, 16, 16, float> acc[3];
    #pragma unroll
    for (int t = 0; t < 3; ++t) wmma::fill_fragment(acc[t], 0.f);

    stage(0);

    #pragma unroll 1
    for (int k = 0; k < 27; ++k) {
        __syncthreads();                 // prev compute done; buf (k+1)&1 reusable
        if (k + 1 < 27) { stage(k + 1); cp_wait<1>(); }
        else cp_wait<0>();
        __syncthreads();                 // buf k visible to all warps

        char* base = dsm + (k & 1) * 39424;
        __nv_bfloat16* Ah = (__nv_bfloat16*)(base);
        __nv_bfloat16* Al = (__nv_bfloat16*)(base + 14336);
        __nv_bfloat16* Bh = (__nv_bfloat16*)(base + 28672);
        __nv_bfloat16* Bl = (__nv_bfloat16*)(base + 34048);

        #pragma unroll
        for (int kf = 0; kf < 3; ++kf) {
            wmma::fragment<wmma::matrix_a, 16, 16, 16, __nv_bfloat16, wmma::row_major> a_hi, a_lo;
            wmma::load_matrix_sync(a_hi, Ah + (wid * 16) * 56 + kf * 16, 56);
            wmma::load_matrix_sync(a_lo, Al + (wid * 16) * 56 + kf * 16, 56);
            #pragma unroll
            for (int nt = 0; nt < 3; ++nt) {
                wmma::fragment<wmma::matrix_b, 16, 16, 16, __nv_bfloat16, wmma::row_major> b_hi, b_lo;
                wmma::load_matrix_sync(b_hi, Bh + (kf * 16) * 56 + nt * 16, 56);
                wmma::load_matrix_sync(b_lo, Bl + (kf * 16) * 56 + nt * 16, 56);
                wmma::mma_sync(acc[nt], a_hi, b_hi, acc[nt]);
                wmma::mma_sync(acc[nt], a_hi, b_lo, acc[nt]);
                wmma::mma_sync(acc[nt], a_lo, b_hi, acc[nt]);
            }
        }
    }

    __syncthreads();
    float* Yf = (float*)dsm;
    #pragma unroll
    for (int nt = 0; nt < 3; ++nt)
        wmma::store_matrix_sync(Yf + (wid * 16) * 48 + nt * 16, acc[nt], 48,
                                wmma::mem_row_major);
    __syncthreads();
    {
        const int row = tid >> 1, half = tid & 1;
        float4* dst = (float4*)(y + (size_t)(n0 + row) * 48 + half * 24);
        const float4* src = (const float4*)(Yf + row * 48 + half * 24);
        #pragma unroll
        for (int q = 0; q < 6; ++q) dst[q] = src[q];
    }
    if (tid < 192) {
        int c = tid % 48, seg = tid / 48;
        float s = 0.f, q = 0.f;
        #pragma unroll 4
        for (int r = seg * 32; r < seg * 32 + 32; ++r) {
            float v = Yf[r * 48 + c];
            s += v; q += v * v;
        }
        sh_stat[seg * 96 + c] = s;
        sh_stat[seg * 96 + 48 + c] = q;
    }
    __syncthreads();
    if (tid < 96) {
        float t = sh_stat[tid] + sh_stat[96 + tid] + sh_stat[192 + tid] + sh_stat[288 + tid];
        atomicAdd(&stats[tid], t);
    }
    __syncthreads();
    if (tid == 0) {
        __threadfence();
        s_last = (atomicAdd(ctr, 1u) == gridDim.x - 1);
    }
    __syncthreads();
    if (s_last && tid < 48) {
        float su = __ldcg(&stats[tid]);
        float qq = __ldcg(&stats[48 + tid]);
        float mu = su / (float)N1;
        float var = fmaxf(qq / (float)N1 - mu * mu, 0.f);
        float sc = g[tid] * rsqrtf(var + BN_EPS);
        sbout[tid] = sc;
        sbout[48 + tid] = b[tid] - mu * sc;
    }
}

// ---------------------------------------------------------------------------
// Stage E: wmma, 64 rows x 48 cols per block (d-split 2, kz=3, KPB=9).
// Dyn smem/buffer: Ah 13312 | Al 13312 | Bh 10752 | Bl 10752 = 48128; x2.
// Writes pE[z]; combine does stats + finalize.
// ---------------------------------------------------------------------------
__global__ void __launch_bounds__(128, 2) convE_wmma(
    const __nv_bfloat16* __restrict__ xhl, const int* __restrict__ neigh,
    const __nv_bfloat16* __restrict__ wph, const __nv_bfloat16* __restrict__ wpl,
    float* __restrict__ pE)
{
    extern __shared__ __align__(16) char dsm[];
    const int tid = threadIdx.x;
    const int wid = tid >> 5;
    const int n0 = blockIdx.x * 64;
    const int dbase = blockIdx.y * 48;
    const int k0 = blockIdx.z * 9;

    auto stage = [&](int i) {
        char* base = dsm + (i & 1) * 48128;
        int k = k0 + i;
        #pragma unroll
        for (int j = 0; j < 12; ++j) {
            int m = tid + 128 * j;           // 1536 = 64 rows x 24 chunks
            int row = m / 24, ch = m % 24;
            int gi = __ldg(&neigh[(size_t)(n0 + row) * 27 + k]);
            const char* src = (const char*)(xhl + (size_t)gi * 256)
                              + (ch < 12 ? ch * 16 : 256 + (ch - 12) * 16);
            char* dst = (ch < 12) ? base + row * 208 + ch * 16
                                  : base + 13312 + row * 208 + (ch - 12) * 16;
            cp16(dst, src);
        }
        #pragma unroll
        for (int t = tid; t < 1152; t += 128) {
            int plane = t / 576, e = t % 576;
            int c = e / 6, cc = e % 6;
            const __nv_bfloat16* wsrc = (plane ? wpl : wph)
                + (size_t)k * 9216 + c * 96 + dbase + cc * 8;
            char* dst = base + (plane ? 37376 : 26624) + c * 112 + cc * 16;
            cp16(dst, (const char*)wsrc);
        }
        cp_commit();
    };

    wmma::fragment<wmma::accumulator, 16, 16, 16, float> acc[3];
    #pragma unroll
    for (int t = 0; t < 3; ++t) wmma::fill_fragment(acc[t], 0.f);

    stage(0);

    #pragma unroll 1
    for (int i = 0; i < 9; ++i) {
        __syncthreads();
        if (i + 1 < 9) { stage(i + 1); cp_wait<1>(); }
        else cp_wait<0>();
        __syncthreads();

        char* base = dsm + (i & 1) * 48128;
        __nv_bfloat16* Ah = (__nv_bfloat16*)(base);
        __nv_bfloat16* Al = (__nv_bfloat16*)(base + 13312);
        __nv_bfloat16* Bh = (__nv_bfloat16*)(base + 26624);
        __nv_bfloat16* Bl = (__nv_bfloat16*)(base + 37376);

        #pragma unroll
        for (int kf = 0; kf < 6; ++kf) {
            wmma::fragment<wmma::matrix_a, 16, 16, 16, __nv_bfloat16, wmma::row_major> a_hi, a_lo;
            wmma::load_matrix_sync(a_hi, Ah + (wid * 16) * 104 + kf * 16, 104);
            wmma::load_matrix_sync(a_lo, Al + (wid * 16) * 104 + kf * 16, 104);
            #pragma unroll
            for (int nt = 0; nt < 3; ++nt) {
                wmma::fragment<wmma::matrix_b, 16, 16, 16, __nv_bfloat16, wmma::row_major> b_hi, b_lo;
                wmma::load_matrix_sync(b_hi, Bh + (kf * 16) * 56 + nt * 16, 56);
                wmma::load_matrix_sync(b_lo, Bl + (kf * 16) * 56 + nt * 16, 56);
                wmma::mma_sync(acc[nt], a_hi, b_hi, acc[nt]);
                wmma::mma_sync(acc[nt], a_hi, b_lo, acc[nt]);
                wmma::mma_sync(acc[nt], a_lo, b_hi, acc[nt]);
            }
        }
    }

    __syncthreads();
    float* Yf = (float*)dsm;
    #pragma unroll
    for (int nt = 0; nt < 3; ++nt)
        wmma::store_matrix_sync(Yf + (wid * 16) * 48 + nt * 16, acc[nt], 48,
                                wmma::mem_row_major);
    __syncthreads();
    {
        const int row = tid >> 1, half = tid & 1;
        float4* dst = (float4*)(pE + ((size_t)blockIdx.z * N2 + n0 + row) * 96
                                + dbase + half * 24);
        const float4* src = (const float4*)(Yf + row * 48 + half * 24);
        #pragma unroll
        for (int q = 0; q < 6; ++q) dst[q] = src[q];
    }
}

// ---------------------------------------------------------------------------
// Combine KZ partials -> y (float4 lanes), stats, last-block BN finalize.
// ---------------------------------------------------------------------------
template <int C, int KZ, int TB, bool WRITE_Y>
__global__ void __launch_bounds__(256) combine_kernel(
    const float* __restrict__ p, float* __restrict__ y, int N,
    float* __restrict__ stats, const float* __restrict__ g,
    const float* __restrict__ b, float* __restrict__ sbout,
    u32* __restrict__ ctr, float invN)
{
    constexpr int V4 = C / 4;
    const int c4 = threadIdx.x;
    const int ty = threadIdx.y;

    float4 s = make_float4(0.f, 0.f, 0.f, 0.f);
    float4 q = make_float4(0.f, 0.f, 0.f, 0.f);

    #pragma unroll 2
    for (int r = blockIdx.x * TB + ty; r < N; r += gridDim.x * TB) {
        float4 v = *(const float4*)(p + (size_t)r * C + 4 * c4);
        #pragma unroll
        for (int z = 1; z < KZ; ++z) {
            float4 t = *(const float4*)(p + ((size_t)z * N + r) * C + 4 * c4);
            v.x += t.x; v.y += t.y; v.z += t.z; v.w += t.w;
        }
        if (WRITE_Y) *(float4*)(y + (size_t)r * C + 4 * c4) = v;
        s.x += v.x; s.y += v.y; s.z += v.z; s.w += v.w;
        q.x += v.x * v.x; q.y += v.y * v.y; q.z += v.z * v.z; q.w += v.w * v.w;
    }

    __shared__ float4 shs[TB][V4];
    __shared__ float4 shq[TB][V4];
    __shared__ bool last;
    shs[ty][c4] = s; shq[ty][c4] = q;
    __syncthreads();

    if (ty == 0) {
        #pragma unroll 4
        for (int j = 1; j < TB; ++j) {
            float4 a = shs[j][c4], d = shq[j][c4];
            s.x += a.x; s.y += a.y; s.z += a.z; s.w += a.w;
            q.x += d.x; q.y += d.y; q.z += d.z; q.w += d.w;
        }
        atomicAdd(&stats[4 * c4 + 0], s.x);
        atomicAdd(&stats[4 * c4 + 1], s.y);
        atomicAdd(&stats[4 * c4 + 2], s.z);
        atomicAdd(&stats[4 * c4 + 3], s.w);
        atomicAdd(&stats[C + 4 * c4 + 0], q.x);
        atomicAdd(&stats[C + 4 * c4 + 1], q.y);
        atomicAdd(&stats[C + 4 * c4 + 2], q.z);
        atomicAdd(&stats[C + 4 * c4 + 3], q.w);
        __threadfence();
    }
    __syncthreads();
    if (ty == 0 && c4 == 0)
        last = (atomicAdd(ctr, 1u) == gridDim.x - 1);
    __syncthreads();
    if (last && ty == 0) {
        #pragma unroll
        for (int j = 0; j < 4; ++j) {
            int c = 4 * c4 + j;
            float su = __ldcg(&stats[c]);
            float qq = __ldcg(&stats[C + c]);
            float mu = su * invN;
            float var = fmaxf(qq * invN - mu * mu, 0.f);
            float sc = g[c] * rsqrtf(var + BN_EPS);
            sbout[c] = sc;
            sbout[C + c] = b[c] - mu * sc;
        }
    }
}

__global__ void norm_out_kernel(float* __restrict__ out, const float* __restrict__ sb) {
    int i = blockIdx.x * 256 + threadIdx.x;
    if (i < N2 * 96) {
        int c = i % 96;
        out[i] = fmaxf(out[i] * sb[c] + sb[96 + c], 0.f);
    }
}

// ---------------------------------------------------------------------------
extern "C" void kernel_launch(void* const* d_in, const int* in_sizes, int n_in,
                              void* d_out, int out_size)
{
    const float* data   = (const float*)d_in[0];
    const int* neigh0 = (const int*)d_in[1];
    const int* child0 = (const int*)d_in[2];
    const int* neigh1 = (const int*)d_in[3];
    const int* child1 = (const int*)d_in[4];
    const int* neigh2 = (const int*)d_in[5];
    const float* w0 = (const float*)d_in[6];
    const float* g0 = (const float*)d_in[7];
    const float* b0 = (const float*)d_in[8];
    const float* wd0 = (const float*)d_in[9];
    const float* gd0 = (const float*)d_in[10];
    const float* bd0 = (const float*)d_in[11];
    const float* w1 = (const float*)d_in[12];
    const float* g1 = (const float*)d_in[13];
    const float* b1 = (const float*)d_in[14];
    const float* wd1 = (const float*)d_in[15];
    const float* gd1 = (const float*)d_in[16];
    const float* bd1 = (const float*)d_in[17];
    const float* wp = (const float*)d_in[18];
    const float* gp = (const float*)d_in[19];
    const float* bp = (const float*)d_in[20];
    float* out = (float*)d_out;

    float *x4p, *y0p, *y1p, *y2p, *y3p, *pDp, *pEp, *stp, *sbp;
    __nv_bfloat16 *y1hlp, *y3hlp, *whp, *wlp, *wphp, *wplp;
    u32* ctrp;
    cudaGetSymbolAddress((void**)&x4p, g_x4);
    cudaGetSymbolAddress((void**)&y0p, g_y0);
    cudaGetSymbolAddress((void**)&y1p, g_y1);
    cudaGetSymbolAddress((void**)&y2p, g_y2);
    cudaGetSymbolAddress((void**)&y3p, g_y3);
    cudaGetSymbolAddress((void**)&y1hlp, g_y1hl);
    cudaGetSymbolAddress((void**)&y3hlp, g_y3hl);
    cudaGetSymbolAddress((void**)&whp, g_wh);
    cudaGetSymbolAddress((void**)&wlp, g_wl);
    cudaGetSymbolAddress((void**)&wphp, g_wph);
    cudaGetSymbolAddress((void**)&wplp, g_wpl);
    cudaGetSymbolAddress((void**)&pDp, g_pD);
    cudaGetSymbolAddress((void**)&pEp, g_pE);
    cudaGetSymbolAddress((void**)&stp, g_stats);
    cudaGetSymbolAddress((void**)&sbp, g_sb);
    cudaGetSymbolAddress((void**)&ctrp, g_ctr);

    const int C_SMEM = 2 * 39424;
    const int E_SMEM = 2 * 48128;
    cudaFuncSetAttribute(convC_wmma, cudaFuncAttributeMaxDynamicSharedMemorySize, C_SMEM);
    cudaFuncSetAttribute(convE_wmma, cudaFuncAttributeMaxDynamicSharedMemorySize, E_SMEM);

    pad_kernel<<<N0 / 256, 256>>>(data, w1, wp);

    // A: x4 -> y0[N0,24], fused stats -> sb0
    convA_kernel<<<N0 / 512, 256>>>((const float4*)x4p, neigh0, w0, y0p,
                                    stp + 0, g0, b0, sbp + 0, ctrp + 0);

    // B: y0 -> y1[N1,48], K=8 whole-K, fused stats -> sb1
    gemm_kernel<8, 8, 24, 48, 6, true, true><<<dim3(N1 / 64, 1, 1), 128>>>(
        y0p, child0, wd0, sbp + 0, y1p, N1,
        stp + 192, gd0, bd0, sbp + 192, ctrp + 1, 1.f / N1);

    // prep: y1 -> padded interleaved bf16 hi/lo rows (BN+ReLU applied)
    prepY_kernel<<<(N1 * 12 + 255) / 256, 256>>>(y1p, sbp + 192);

    // C: monolithic wmma, pipelined, fused stats -> y2 + sb2
    convC_wmma<<<N1 / 128, 256, C_SMEM>>>(
        y1hlp, neigh1, whp, wlp, y2p,
        stp + 384, g1, b1, sbp + 384, ctrp + 2);

    // D: y2 -> pD (kz=8) -> combine -> y3 + sb3
    gemm_kernel<8, 1, 48, 96, 12, true, false><<<dim3(N2 / 64, 1, 8), 128>>>(
        y2p, child1, wd1, sbp + 384, pDp, N2,
        nullptr, nullptr, nullptr, nullptr, nullptr, 0.f);
    combine_kernel<96, 8, 10, true><<<256, dim3(24, 10)>>>(
        pDp, y3p, N2, stp + 576, gd1, bd1, sbp + 576, ctrp + 3, 1.f / N2);

    // prepE: y3 -> padded interleaved bf16 hi/lo rows (BN+ReLU applied)
    prepE_kernel<<<(N2 * 24 + 255) / 256, 256>>>(y3p, sbp + 576);

    // E: wmma (kz=3, d-split 2) -> pE -> combine -> out(raw) + sb4
    convE_wmma<<<dim3(N2 / 64, 2, 3), 128, E_SMEM>>>(
        y3hlp, neigh2, wphp, wplp, pEp);
    combine_kernel<96, 3, 10, true><<<256, dim3(24, 10)>>>(
        pEp, out, N2, stp + 768, gp, bp, sbp + 768, ctrp + 4, 1.f / N2);

    norm_out_kernel<<<(N2 * 96 + 255) / 256, 256>>>(out, sbp + 768);
}

// round 16
// speedup vs baseline: 1.0171x; 1.0171x over previous
#include <cuda_runtime.h>
#include <cuda_bf16.h>
#include <mma.h>

using namespace nvcuda;

#define N0 262144
#define N1 32768
#define N2 4096
#define BN_EPS 1e-5f

typedef unsigned long long u64;
typedef unsigned int u32;

__device__ __forceinline__ u64 pack2(float v) {
    u64 r; asm("mov.b64 %0, {%1, %1};" : "=l"(r) : "f"(v)); return r;
}
__device__ __forceinline__ void fma2(u64& d, u64 a, u64 b) {
    asm("fma.rn.f32x2 %0, %1, %2, %0;" : "+l"(d) : "l"(a), "l"(b));
}
__device__ __forceinline__ void unpack2(u64 v, float& lo, float& hi) {
    asm("mov.b64 {%0, %1}, %2;" : "=f"(lo), "=f"(hi) : "l"(v));
}
__device__ __forceinline__ void cp16(void* smem, const void* gmem) {
    u32 sa = (u32)__cvta_generic_to_shared(smem);
    asm volatile("cp.async.cg.shared.global [%0], [%1], 16;" :: "r"(sa), "l"(gmem));
}
__device__ __forceinline__ void cp_commit() { asm volatile("cp.async.commit_group;"); }
template <int W_> __device__ __forceinline__ void cp_wait() {
    asm volatile("cp.async.wait_group %0;" :: "n"(W_));
}
__device__ __forceinline__ u32 pack_bf16x2(float a, float b) {
    __nv_bfloat162 t = __floats2bfloat162_rn(a, b);
    return *(u32*)&t;
}

// ---------------- static scratch ----------------
__device__ float4 g_x4[N0];
__device__ float g_y0[N0 * 24];
__device__ float g_y1[N1 * 48];
__device__ float g_y2[N1 * 48];
__device__ float g_y3[N2 * 96];
__device__ __nv_bfloat16 g_y1hl[N1 * 128];   // 256B rows: hi@0(96B pad 128), lo@128B
__device__ __nv_bfloat16 g_wh[27 * 48 * 48];
__device__ __nv_bfloat16 g_wl[27 * 48 * 48];
__device__ float g_pD[8 * N2 * 96];
__device__ float g_pE[9 * N2 * 96];
__device__ float g_stats[5 * 192];
__device__ float g_sb[5 * 192];
__device__ u32   g_ctr[8];

// pad + init + W1 bf16-split, all fused
__global__ void pad_kernel(const float* __restrict__ d, const float* __restrict__ w1) {
    int i = blockIdx.x * 256 + threadIdx.x;
    if (blockIdx.x == 0) {
        int t = threadIdx.x;
        for (int j = t; j < 5 * 192; j += 256) g_stats[j] = 0.f;
        if (t < 8) g_ctr[t] = 0u;
    }
    if (i < 27 * 48 * 48) {
        float w = w1[i];
        __nv_bfloat16 h = __float2bfloat16(w);
        g_wh[i] = h;
        g_wl[i] = __float2bfloat16(w - __bfloat162float(h));
    }
    if (i < N0) {
        float4 v;
        v.x = d[3 * i]; v.y = d[3 * i + 1]; v.z = d[3 * i + 2]; v.w = 0.f;
        g_x4[i] = v;
    }
}

// ---------------------------------------------------------------------------
// Stage A: per-thread, 2 rows/thread, CIN=3 -> COUT=24, K=27. Fused stats.
// ---------------------------------------------------------------------------
__global__ void __launch_bounds__(256, 2) convA_kernel(
    const float4* __restrict__ x4, const int* __restrict__ neigh,
    const float* __restrict__ W, float* __restrict__ y,
    float* __restrict__ stats, const float* __restrict__ g,
    const float* __restrict__ b, float* __restrict__ sbout,
    u32* __restrict__ ctr)
{
    __shared__ __align__(16) float sh_w[27 * 3 * 24];
    __shared__ int sh_idx[512 * 3];
    __shared__ float sh_stat[8 * 48];
    __shared__ bool s_last;

    const int tid = threadIdx.x;
    const int n0 = blockIdx.x * 512;

    for (int i = tid; i < 27 * 3 * 24 / 4; i += 256) cp16(sh_w + 4 * i, W + 4 * i);
    cp_commit(); cp_wait<0>();

    u64 acc[2][12] = {};

    #pragma unroll 1
    for (int kt = 0; kt < 27; kt += 3) {
        __syncthreads();
        #pragma unroll 1
        for (int i = tid; i < 512 * 3; i += 256) {
            int row = i / 3, kk = i % 3;
            sh_idx[i] = neigh[(size_t)(n0 + row) * 27 + kt + kk];
        }
        __syncthreads();
        #pragma unroll
        for (int k2 = 0; k2 < 3; ++k2) {
            int i0 = sh_idx[(2 * tid) * 3 + k2];
            int i1 = sh_idx[(2 * tid + 1) * 3 + k2];
            float4 v0 = x4[i0], v1 = x4[i1];
            const float* wk = sh_w + (kt + k2) * 72;
            #pragma unroll
            for (int c = 0; c < 3; ++c) {
                u64 p0 = pack2(c == 0 ? v0.x : (c == 1 ? v0.y : v0.z));
                u64 p1 = pack2(c == 0 ? v1.x : (c == 1 ? v1.y : v1.z));
                const ulonglong2* wr = (const ulonglong2*)(wk + c * 24);
                #pragma unroll
                for (int j = 0; j < 6; ++j) {
                    ulonglong2 wv = wr[j];
                    fma2(acc[0][2 * j],     p0, wv.x);
                    fma2(acc[0][2 * j + 1], p0, wv.y);
                    fma2(acc[1][2 * j],     p1, wv.x);
                    fma2(acc[1][2 * j + 1], p1, wv.y);
                }
            }
        }
    }

    #pragma unroll
    for (int r = 0; r < 2; ++r) {
        u64* yr = (u64*)(y + (size_t)(n0 + 2 * tid + r) * 24);
        #pragma unroll
        for (int j = 0; j < 12; ++j) yr[j] = acc[r][j];
    }

    const int wid = tid >> 5;
    #pragma unroll 1
    for (int j = 0; j < 12; ++j) {
        float lo0, hi0, lo1, hi1;
        unpack2(acc[0][j], lo0, hi0);
        unpack2(acc[1][j], lo1, hi1);
        float s0 = lo0 + lo1, s1 = hi0 + hi1;
        float q0 = lo0 * lo0 + lo1 * lo1, q1 = hi0 * hi0 + hi1 * hi1;
        #pragma unroll
        for (int o = 16; o; o >>= 1) {
            s0 += __shfl_xor_sync(~0u, s0, o);
            s1 += __shfl_xor_sync(~0u, s1, o);
            q0 += __shfl_xor_sync(~0u, q0, o);
            q1 += __shfl_xor_sync(~0u, q1, o);
        }
        if ((tid & 31) == 0) {
            float* row = sh_stat + wid * 48;
            row[2 * j] = s0;  row[2 * j + 1] = s1;
            row[24 + 2 * j] = q0;  row[24 + 2 * j + 1] = q1;
        }
    }
    __syncthreads();
    if (tid < 48) {
        float t = 0.f;
        #pragma unroll
        for (int w = 0; w < 8; ++w) t += sh_stat[w * 48 + tid];
        atomicAdd(&stats[tid], t);
    }
    __syncthreads();
    if (tid == 0) {
        __threadfence();
        s_last = (atomicAdd(ctr, 1u) == gridDim.x - 1);
    }
    __syncthreads();
    if (s_last && tid < 24) {
        float su = __ldcg(&stats[tid]);
        float qq = __ldcg(&stats[24 + tid]);
        float mu = su / (float)N0;
        float var = fmaxf(qq / (float)N0 - mu * mu, 0.f);
        float sc = g[tid] * rsqrtf(var + BN_EPS);
        sbout[tid] = sc;
        sbout[24 + tid] = b[tid] - mu * sc;
    }
}

// ---------------------------------------------------------------------------
// Scalar tiled gather-GEMM (stages B, D, E). 128-thread block, 64-row tile.
// ---------------------------------------------------------------------------
template <int K, int KPB, int CIN, int COUT, int TD, bool NORM_IN, bool FUSE>
__global__ void __launch_bounds__(128, (TD == 6 ? 6 : 4)) gemm_kernel(
    const float* __restrict__ x, const int* __restrict__ neigh,
    const float* __restrict__ W, const float* __restrict__ sb,
    float* __restrict__ y, int N,
    float* __restrict__ stats, const float* __restrict__ g,
    const float* __restrict__ b, float* __restrict__ sbout,
    u32* __restrict__ ctr, float invN)
{
    constexpr int CC = 24;
    constexpr int NCC = CIN / CC;
    constexpr int CHUNKS = KPB * NCC;
    constexpr int DG = COUT / TD;
    constexpr int XP = 68;
    constexpr int NW = 4;

    __shared__ float sh_x[2][CC * XP];
    __shared__ __align__(16) float sh_w[2][CC * COUT];
    __shared__ float sh_s[NORM_IN ? 2 * CIN : 1];
    __shared__ float sh_stat[FUSE ? NW * 2 * COUT : 1];
    __shared__ bool s_last;

    const int tid = threadIdx.x;
    const int n0 = blockIdx.x * 64;
    const int k0 = blockIdx.z * KPB;
    const int rg = tid / DG;
    const int td = tid % DG;

    auto stageW = [&](int chunk) {
        int k = chunk / NCC, cc = chunk % NCC;
        const float* src = W + ((size_t)(k0 + k) * CIN + cc * CC) * COUT;
        float* dst = sh_w[chunk & 1];
        #pragma unroll 1
        for (int i = tid; i < CC * COUT / 4; i += 128) cp16(dst + 4 * i, src + 4 * i);
        cp_commit();
    };
    auto gather = [&](int chunk, float4* xr) {
        int k = chunk / NCC, cc = chunk % NCC;
        #pragma unroll
        for (int j = 0; j < 3; ++j) {
            int m = tid + 128 * j;
            int row = m / 6, f4 = m % 6;
            int gi = __ldg(&neigh[(size_t)(n0 + row) * K + k0 + k]);
            xr[j] = *(const float4*)(x + (size_t)gi * CIN + cc * CC + f4 * 4);
        }
    };
    auto stsX = [&](int chunk, const float4* xr) {
        int cc = chunk % NCC;
        float* dst = sh_x[chunk & 1];
        #pragma unroll
        for (int j = 0; j < 3; ++j) {
            int m = tid + 128 * j;
            int row = m / 6, f4 = m % 6;
            float4 v = xr[j];
            if (NORM_IN) {
                int gc = cc * CC + 4 * f4;
                v.x = fmaxf(v.x * sh_s[gc + 0] + sh_s[CIN + gc + 0], 0.f);
                v.y = fmaxf(v.y * sh_s[gc + 1] + sh_s[CIN + gc + 1], 0.f);
                v.z = fmaxf(v.z * sh_s[gc + 2] + sh_s[CIN + gc + 2], 0.f);
                v.w = fmaxf(v.w * sh_s[gc + 3] + sh_s[CIN + gc + 3], 0.f);
            }
            dst[(4 * f4 + 0) * XP + row] = v.x;
            dst[(4 * f4 + 1) * XP + row] = v.y;
            dst[(4 * f4 + 2) * XP + row] = v.z;
            dst[(4 * f4 + 3) * XP + row] = v.w;
        }
    };

    u64 acc[4][TD / 2] = {};
    float4 xr[3];

    stageW(0);
    if (NORM_IN)
        for (int i = tid; i < 2 * CIN; i += 128) sh_s[i] = sb[i];
    gather(0, xr);
    cp_wait<0>();
    __syncthreads();
    stsX(0, xr);

    #pragma unroll 1
    for (int i = 0; i < CHUNKS; ++i) {
        __syncthreads();
        if (i + 1 < CHUNKS) { gather(i + 1, xr); stageW(i + 1); }

        const float* wb = sh_w[i & 1];
        const float* xb = sh_x[i & 1];
        #pragma unroll
        for (int c = 0; c < CC; ++c) {
            float4 xv = *(const float4*)&xb[c * XP + 4 * rg];
            u64 P[4] = {pack2(xv.x), pack2(xv.y), pack2(xv.z), pack2(xv.w)};
            const float* wc = wb + c * COUT + td * TD;
            u64 wv[TD / 2];
            if (TD == 6) {
                wv[0] = *(const u64*)(wc + 0);
                wv[1] = *(const u64*)(wc + 2);
                wv[2] = *(const u64*)(wc + 4);
            } else {
                ulonglong2 q0 = *(const ulonglong2*)(wc + 0);
                ulonglong2 q1 = *(const ulonglong2*)(wc + 4);
                ulonglong2 q2 = *(const ulonglong2*)(wc + 8);
                wv[0] = q0.x; wv[1] = q0.y; wv[2] = q1.x;
                wv[3] = q1.y; wv[4] = q2.x; wv[5] = q2.y;
            }
            #pragma unroll
            for (int r = 0; r < 4; ++r)
                #pragma unroll
                for (int j = 0; j < TD / 2; ++j)
                    fma2(acc[r][j], P[r], wv[j]);
        }

        if (i + 1 < CHUNKS) stsX(i + 1, xr);
        cp_wait<0>();
    }

    #pragma unroll
    for (int r = 0; r < 4; ++r) {
        float* yr = y + ((size_t)blockIdx.z * N + n0 + 4 * rg + r) * COUT + td * TD;
        #pragma unroll
        for (int j = 0; j < TD / 2; ++j) *(u64*)(yr + 2 * j) = acc[r][j];
    }

    if (FUSE) {
        const int w = tid >> 5, lane = tid & 31;
        float sA[TD], qA[TD];
        #pragma unroll
        for (int j = 0; j < TD / 2; ++j) {
            float s0 = 0.f, s1 = 0.f, q0 = 0.f, q1 = 0.f;
            #pragma unroll
            for (int r = 0; r < 4; ++r) {
                float lo, hi; unpack2(acc[r][j], lo, hi);
                s0 += lo; s1 += hi; q0 += lo * lo; q1 += hi * hi;
            }
            sA[2 * j] = s0; sA[2 * j + 1] = s1;
            qA[2 * j] = q0; qA[2 * j + 1] = q1;
        }
        #pragma unroll
        for (int o = 8; o < 32; o <<= 1)
            #pragma unroll
            for (int t = 0; t < TD; ++t) {
                sA[t] += __shfl_xor_sync(~0u, sA[t], o);
                qA[t] += __shfl_xor_sync(~0u, qA[t], o);
            }
        if (lane < 8) {
            int base = w * 2 * COUT;
            #pragma unroll
            for (int t = 0; t < TD; ++t) {
                sh_stat[base + lane * TD + t] = sA[t];
                sh_stat[base + COUT + lane * TD + t] = qA[t];
            }
        }
        __syncthreads();
        if (tid < 2 * COUT) {
            float tot = 0.f;
            #pragma unroll
            for (int w2 = 0; w2 < NW; ++w2) tot += sh_stat[w2 * 2 * COUT + tid];
            atomicAdd(&stats[tid], tot);
        }
        __syncthreads();
        if (tid == 0) {
            __threadfence();
            s_last = (atomicAdd(ctr, 1u) == gridDim.x - 1);
        }
        __syncthreads();
        if (s_last && tid < COUT) {
            float su = __ldcg(&stats[tid]);
            float qq = __ldcg(&stats[COUT + tid]);
            float mu = su * invN;
            float var = fmaxf(qq * invN - mu * mu, 0.f);
            float sc = g[tid] * rsqrtf(var + BN_EPS);
            sbout[tid] = sc;
            sbout[COUT + tid] = b[tid] - mu * sc;
        }
    }
}

// ---------------------------------------------------------------------------
// Stage C: monolithic wmma with FUSED prep (y1 -> bf16 hi/lo planes) and a
// grid-wide spin sync (grid 256 fully resident at 2 CTA/SM). Fused stats.
// ---------------------------------------------------------------------------
__global__ void __launch_bounds__(256, 2) convC_wmma(
    const float* __restrict__ y1, const float* __restrict__ sbin,
    __nv_bfloat16* __restrict__ xhl, u32* __restrict__ syncc,
    const int* __restrict__ neigh,
    const __nv_bfloat16* __restrict__ wh, const __nv_bfloat16* __restrict__ wl,
    float* __restrict__ y,
    float* __restrict__ stats, const float* __restrict__ g,
    const float* __restrict__ b, float* __restrict__ sbout,
    u32* __restrict__ ctr)
{
    extern __shared__ __align__(16) char dsm[];
    __shared__ float sh_stat[4 * 96];
    __shared__ bool s_last;

    const int tid = threadIdx.x;
    const int wid = tid >> 5;
    const int n0 = blockIdx.x * 128;

    // ---- fused prep: convert this block's 128-row slice of y1 ----
    {
        const int base4 = blockIdx.x * 1536;   // float4 units
        #pragma unroll
        for (int j = 0; j < 6; ++j) {
            int idx = base4 + tid + 256 * j;
            int e = idx * 4;
            int row = e / 48, c = e % 48;
            float4 v = *(const float4*)(y1 + e);
            v.x = fmaxf(v.x * sbin[c + 0] + sbin[48 + c + 0], 0.f);
            v.y = fmaxf(v.y * sbin[c + 1] + sbin[48 + c + 1], 0.f);
            v.z = fmaxf(v.z * sbin[c + 2] + sbin[48 + c + 2], 0.f);
            v.w = fmaxf(v.w * sbin[c + 3] + sbin[48 + c + 3], 0.f);
            u32 h01 = pack_bf16x2(v.x, v.y);
            u32 h23 = pack_bf16x2(v.z, v.w);
            float2 f01 = __bfloat1622float2(*(__nv_bfloat162*)&h01);
            float2 f23 = __bfloat1622float2(*(__nv_bfloat162*)&h23);
            u32 l01 = pack_bf16x2(v.x - f01.x, v.y - f01.y);
            u32 l23 = pack_bf16x2(v.z - f23.x, v.w - f23.y);
            *(u64*)(xhl + (size_t)row * 128 + c)      = (u64)h01 | ((u64)h23 << 32);
            *(u64*)(xhl + (size_t)row * 128 + 64 + c) = (u64)l01 | ((u64)l23 << 32);
        }
        __syncthreads();
        if (tid == 0) {
            __threadfence();
            atomicAdd(syncc, 1u);
            while (*(volatile u32*)syncc < gridDim.x) { }
        }
        __syncthreads();
    }

    const int rp = tid >> 4;
    const int ch = tid & 15;
    const bool isHi = ch < 6;
    const bool isLo = (ch >= 8 && ch < 14);

    auto stage = [&](int k) {
        char* base = dsm + (k & 1) * 39424;
        #pragma unroll
        for (int p = 0; p < 8; ++p) {
            int row = p * 16 + rp;
            int gi = __ldg(&neigh[(size_t)(n0 + row) * 27 + k]);
            const char* src = (const char*)(xhl + (size_t)gi * 128) + ch * 16;
            if (isHi)      cp16(base + row * 112 + ch * 16, src);
            else if (isLo) cp16(base + 14336 + row * 112 + (ch - 8) * 16, src);
        }
        const char* swh = (const char*)(wh + (size_t)k * 2304);
        const char* swl = (const char*)(wl + (size_t)k * 2304);
        #pragma unroll
        for (int t = tid; t < 288; t += 256) {
            int row = t / 6, cc = t % 6;
            cp16(base + 28672 + row * 112 + cc * 16, swh + t * 16);
            cp16(base + 34048 + row * 112 + cc * 16, swl + t * 16);
        }
        cp_commit();
    };

    wmma::fragment<wmma::accumulator, 16, 16, 16, float> acc[3];
    #pragma unroll
    for (int t = 0; t < 3; ++t) wmma::fill_fragment(acc[t], 0.f);

    stage(0);
    cp_wait<0>();

    #pragma unroll 1
    for (int k = 0; k < 27; ++k) {
        __syncthreads();                     // buf(k) visible; prev readers done
        if (k + 1 < 27) stage(k + 1);

        char* base = dsm + (k & 1) * 39424;
        __nv_bfloat16* Ah = (__nv_bfloat16*)(base);
        __nv_bfloat16* Al = (__nv_bfloat16*)(base + 14336);
        __nv_bfloat16* Bh = (__nv_bfloat16*)(base + 28672);
        __nv_bfloat16* Bl = (__nv_bfloat16*)(base + 34048);

        #pragma unroll
        for (int kf = 0; kf < 3; ++kf) {
            wmma::fragment<wmma::matrix_a, 16, 16, 16, __nv_bfloat16, wmma::row_major> a_hi, a_lo;
            wmma::load_matrix_sync(a_hi, Ah + (wid * 16) * 56 + kf * 16, 56);
            wmma::load_matrix_sync(a_lo, Al + (wid * 16) * 56 + kf * 16, 56);
            #pragma unroll
            for (int nt = 0; nt < 3; ++nt) {
                wmma::fragment<wmma::matrix_b, 16, 16, 16, __nv_bfloat16, wmma::row_major> b_hi, b_lo;
                wmma::load_matrix_sync(b_hi, Bh + (kf * 16) * 56 + nt * 16, 56);
                wmma::load_matrix_sync(b_lo, Bl + (kf * 16) * 56 + nt * 16, 56);
                wmma::mma_sync(acc[nt], a_hi, b_hi, acc[nt]);
                wmma::mma_sync(acc[nt], a_hi, b_lo, acc[nt]);
                wmma::mma_sync(acc[nt], a_lo, b_hi, acc[nt]);
            }
        }
        cp_wait<0>();
    }

    // epilogue: fragments -> smem -> global + fused stats
    __syncthreads();
    float* Yf = (float*)dsm;
    #pragma unroll
    for (int nt = 0; nt < 3; ++nt)
        wmma::store_matrix_sync(Yf + (wid * 16) * 48 + nt * 16, acc[nt], 48,
                                wmma::mem_row_major);
    __syncthreads();
    {
        const int row = tid >> 1, half = tid & 1;
        float4* dst = (float4*)(y + (size_t)(n0 + row) * 48 + half * 24);
        const float4* src = (const float4*)(Yf + row * 48 + half * 24);
        #pragma unroll
        for (int q = 0; q < 6; ++q) dst[q] = src[q];
    }
    if (tid < 192) {
        int c = tid % 48, seg = tid / 48;
        float s = 0.f, q = 0.f;
        #pragma unroll 4
        for (int r = seg * 32; r < seg * 32 + 32; ++r) {
            float v = Yf[r * 48 + c];
            s += v; q += v * v;
        }
        sh_stat[seg * 96 + c] = s;
        sh_stat[seg * 96 + 48 + c] = q;
    }
    __syncthreads();
    if (tid < 96) {
        float t = sh_stat[tid] + sh_stat[96 + tid] + sh_stat[192 + tid] + sh_stat[288 + tid];
        atomicAdd(&stats[tid], t);
    }
    __syncthreads();
    if (tid == 0) {
        __threadfence();
        s_last = (atomicAdd(ctr, 1u) == gridDim.x - 1);
    }
    __syncthreads();
    if (s_last && tid < 48) {
        float su = __ldcg(&stats[tid]);
        float qq = __ldcg(&stats[48 + tid]);
        float mu = su / (float)N1;
        float var = fmaxf(qq / (float)N1 - mu * mu, 0.f);
        float sc = g[tid] * rsqrtf(var + BN_EPS);
        sbout[tid] = sc;
        sbout[48 + tid] = b[tid] - mu * sc;
    }
}

// ---------------------------------------------------------------------------
// Combine KZ partials -> y (float4 lanes), stats, last-block BN finalize.
// ---------------------------------------------------------------------------
template <int C, int KZ, int TB, bool WRITE_Y>
__global__ void __launch_bounds__(256) combine_kernel(
    const float* __restrict__ p, float* __restrict__ y, int N,
    float* __restrict__ stats, const float* __restrict__ g,
    const float* __restrict__ b, float* __restrict__ sbout,
    u32* __restrict__ ctr, float invN)
{
    constexpr int V4 = C / 4;
    const int c4 = threadIdx.x;
    const int ty = threadIdx.y;

    float4 s = make_float4(0.f, 0.f, 0.f, 0.f);
    float4 q = make_float4(0.f, 0.f, 0.f, 0.f);

    #pragma unroll 2
    for (int r = blockIdx.x * TB + ty; r < N; r += gridDim.x * TB) {
        float4 v = *(const float4*)(p + (size_t)r * C + 4 * c4);
        #pragma unroll
        for (int z = 1; z < KZ; ++z) {
            float4 t = *(const float4*)(p + ((size_t)z * N + r) * C + 4 * c4);
            v.x += t.x; v.y += t.y; v.z += t.z; v.w += t.w;
        }
        if (WRITE_Y) *(float4*)(y + (size_t)r * C + 4 * c4) = v;
        s.x += v.x; s.y += v.y; s.z += v.z; s.w += v.w;
        q.x += v.x * v.x; q.y += v.y * v.y; q.z += v.z * v.z; q.w += v.w * v.w;
    }

    __shared__ float4 shs[TB][V4];
    __shared__ float4 shq[TB][V4];
    __shared__ bool last;
    shs[ty][c4] = s; shq[ty][c4] = q;
    __syncthreads();

    if (ty == 0) {
        #pragma unroll 4
        for (int j = 1; j < TB; ++j) {
            float4 a = shs[j][c4], d = shq[j][c4];
            s.x += a.x; s.y += a.y; s.z += a.z; s.w += a.w;
            q.x += d.x; q.y += d.y; q.z += d.z; q.w += d.w;
        }
        atomicAdd(&stats[4 * c4 + 0], s.x);
        atomicAdd(&stats[4 * c4 + 1], s.y);
        atomicAdd(&stats[4 * c4 + 2], s.z);
        atomicAdd(&stats[4 * c4 + 3], s.w);
        atomicAdd(&stats[C + 4 * c4 + 0], q.x);
        atomicAdd(&stats[C + 4 * c4 + 1], q.y);
        atomicAdd(&stats[C + 4 * c4 + 2], q.z);
        atomicAdd(&stats[C + 4 * c4 + 3], q.w);
        __threadfence();
    }
    __syncthreads();
    if (ty == 0 && c4 == 0)
        last = (atomicAdd(ctr, 1u) == gridDim.x - 1);
    __syncthreads();
    if (last && ty == 0) {
        #pragma unroll
        for (int j = 0; j < 4; ++j) {
            int c = 4 * c4 + j;
            float su = __ldcg(&stats[c]);
            float qq = __ldcg(&stats[C + c]);
            float mu = su * invN;
            float var = fmaxf(qq * invN - mu * mu, 0.f);
            float sc = g[c] * rsqrtf(var + BN_EPS);
            sbout[c] = sc;
            sbout[C + c] = b[c] - mu * sc;
        }
    }
}

__global__ void norm_out_kernel(float* __restrict__ out, const float* __restrict__ sb) {
    int i = blockIdx.x * 256 + threadIdx.x;
    if (i < N2 * 96) {
        int c = i % 96;
        out[i] = fmaxf(out[i] * sb[c] + sb[96 + c], 0.f);
    }
}

// ---------------------------------------------------------------------------
extern "C" void kernel_launch(void* const* d_in, const int* in_sizes, int n_in,
                              void* d_out, int out_size)
{
    const float* data   = (const float*)d_in[0];
    const int* neigh0 = (const int*)d_in[1];
    const int* child0 = (const int*)d_in[2];
    const int* neigh1 = (const int*)d_in[3];
    const int* child1 = (const int*)d_in[4];
    const int* neigh2 = (const int*)d_in[5];
    const float* w0 = (const float*)d_in[6];
    const float* g0 = (const float*)d_in[7];
    const float* b0 = (const float*)d_in[8];
    const float* wd0 = (const float*)d_in[9];
    const float* gd0 = (const float*)d_in[10];
    const float* bd0 = (const float*)d_in[11];
    const float* w1 = (const float*)d_in[12];
    const float* g1 = (const float*)d_in[13];
    const float* b1 = (const float*)d_in[14];
    const float* wd1 = (const float*)d_in[15];
    const float* gd1 = (const float*)d_in[16];
    const float* bd1 = (const float*)d_in[17];
    const float* wp = (const float*)d_in[18];
    const float* gp = (const float*)d_in[19];
    const float* bp = (const float*)d_in[20];
    float* out = (float*)d_out;

    float *x4p, *y0p, *y1p, *y2p, *y3p, *pDp, *pEp, *stp, *sbp;
    __nv_bfloat16 *y1hlp, *whp, *wlp;
    u32* ctrp;
    cudaGetSymbolAddress((void**)&x4p, g_x4);
    cudaGetSymbolAddress((void**)&y0p, g_y0);
    cudaGetSymbolAddress((void**)&y1p, g_y1);
    cudaGetSymbolAddress((void**)&y2p, g_y2);
    cudaGetSymbolAddress((void**)&y3p, g_y3);
    cudaGetSymbolAddress((void**)&y1hlp, g_y1hl);
    cudaGetSymbolAddress((void**)&whp, g_wh);
    cudaGetSymbolAddress((void**)&wlp, g_wl);
    cudaGetSymbolAddress((void**)&pDp, g_pD);
    cudaGetSymbolAddress((void**)&pEp, g_pE);
    cudaGetSymbolAddress((void**)&stp, g_stats);
    cudaGetSymbolAddress((void**)&sbp, g_sb);
    cudaGetSymbolAddress((void**)&ctrp, g_ctr);

    const int C_SMEM = 2 * 39424;  // 78848 B
    cudaFuncSetAttribute(convC_wmma, cudaFuncAttributeMaxDynamicSharedMemorySize, C_SMEM);

    pad_kernel<<<N0 / 256, 256>>>(data, w1);

    // A: x4 -> y0[N0,24], fused stats -> sb0
    convA_kernel<<<N0 / 512, 256>>>((const float4*)x4p, neigh0, w0, y0p,
                                    stp + 0, g0, b0, sbp + 0, ctrp + 0);

    // B: y0 -> y1[N1,48], K=8 whole-K, fused stats -> sb1
    gemm_kernel<8, 8, 24, 48, 6, true, true><<<dim3(N1 / 64, 1, 1), 128>>>(
        y0p, child0, wd0, sbp + 0, y1p, N1,
        stp + 192, gd0, bd0, sbp + 192, ctrp + 1, 1.f / N1);

    // C: fused prep (grid-sync) + monolithic wmma, fused stats -> y2 + sb2
    convC_wmma<<<N1 / 128, 256, C_SMEM>>>(
        y1p, sbp + 192, y1hlp, ctrp + 5, neigh1, whp, wlp, y2p,
        stp + 384, g1, b1, sbp + 384, ctrp + 2);

    // D: y2 -> pD (kz=8) -> combine -> y3 + sb3
    gemm_kernel<8, 1, 48, 96, 12, true, false><<<dim3(N2 / 64, 1, 8), 128>>>(
        y2p, child1, wd1, sbp + 384, pDp, N2,
        nullptr, nullptr, nullptr, nullptr, nullptr, 0.f);
    combine_kernel<96, 8, 10, true><<<256, dim3(24, 10)>>>(
        pDp, y3p, N2, stp + 576, gd1, bd1, sbp + 576, ctrp + 3, 1.f / N2);

    // E: y3 -> pE (kz=9, KPB=3) -> combine -> out(raw) + sb4
    gemm_kernel<27, 3, 96, 96, 12, true, false><<<dim3(N2 / 64, 1, 9), 128>>>(
        y3p, neigh2, wp, sbp + 576, pEp, N2,
        nullptr, nullptr, nullptr, nullptr, nullptr, 0.f);
    combine_kernel<96, 9, 10, true><<<256, dim3(24, 10)>>>(
        pEp, out, N2, stp + 768, gp, bp, sbp + 768, ctrp + 4, 1.f / N2);

    norm_out_kernel<<<(N2 * 96 + 255) / 256, 256>>>(out, sbp + 768);
}